// round 1
// baseline (speedup 1.0000x reference)
#include <cuda_runtime.h>

#define NN 50000
#define EE 800000
#define DD 128
#define BB 5
#define GG 512
#define CC 10

typedef unsigned long long ull;

// ----------------- scratch (static device allocations) -----------------
__device__ float g_bufA[(size_t)NN * DD];   // aggregated input h0
__device__ float g_bufB[(size_t)NN * DD];   // y1 (pre-BN, post-relu)
__device__ float g_bufC[(size_t)NN * DD];   // y2 (pre-BN, post-relu) == next x (affine applied lazily)
__device__ int   g_cnt[NN];
__device__ int   g_rowptr[NN + 1];
__device__ int   g_cursor[NN];
__device__ int   g_col[EE];
__device__ int   g_bcnt[GG];
__device__ int   g_browptr[GG + 1];
__device__ int   g_bcursor[GG];
__device__ int   g_nlist[NN];
__device__ float g_cs1[DD];  __device__ float g_cq1[DD];
__device__ float g_cs2[DD];  __device__ float g_cq2[DD];
__device__ float g_sc1[DD];  __device__ float g_sh1[DD];
__device__ float g_sc2[DD];  __device__ float g_sh2[DD];
__device__ float g_feats[GG * BB * DD];
__device__ float g_fs[BB * DD]; __device__ float g_fh[BB * DD];

// ----------------- packed f32x2 helpers (sm_103a) -----------------
__device__ __forceinline__ ull ffma2u(ull a, ull b, ull c) {
    ull d;
    asm("fma.rn.f32x2 %0, %1, %2, %3;" : "=l"(d) : "l"(a), "l"(b), "l"(c));
    return d;
}
__device__ __forceinline__ ull pack2(float x, float y) {
    ull r;
    asm("mov.b64 %0, {%1, %2};" : "=l"(r) : "f"(x), "f"(y));
    return r;
}
__device__ __forceinline__ void unpack2(ull v, float& lo, float& hi) {
    asm("mov.b64 {%0, %1}, %2;" : "=f"(lo), "=f"(hi) : "l"(v));
}

// ----------------- setup kernels -----------------
__global__ void k_init(int n) {
    int i = blockIdx.x * blockDim.x + threadIdx.x;
    if (i < n) g_cnt[i] = 0;
    if (i < GG) g_bcnt[i] = 0;
    if (i < DD) { g_cs1[i] = 0.f; g_cq1[i] = 0.f; g_cs2[i] = 0.f; g_cq2[i] = 0.f; }
}

__global__ void k_hist(const int* __restrict__ keys, int* __restrict__ cnt, int n) {
    int i = blockIdx.x * blockDim.x + threadIdx.x;
    if (i < n) atomicAdd(&cnt[keys[i]], 1);
}

// single-block chunked exclusive scan; writes rowptr[0..n] and cursor[i]=rowptr[i]
__global__ void k_scan(const int* __restrict__ cnt, int* __restrict__ rowptr,
                       int* __restrict__ cursor, int n) {
    __shared__ int s[1024];
    __shared__ int carry;
    int tid = threadIdx.x;
    if (tid == 0) { carry = 0; rowptr[0] = 0; }
    __syncthreads();
    for (int base = 0; base < n; base += 1024) {
        int i = base + tid;
        int v = (i < n) ? cnt[i] : 0;
        s[tid] = v;
        __syncthreads();
        for (int st = 1; st < 1024; st <<= 1) {
            int t = (tid >= st) ? s[tid - st] : 0;
            __syncthreads();
            s[tid] += t;
            __syncthreads();
        }
        int incl = s[tid] + carry;
        if (i < n) { rowptr[i + 1] = incl; cursor[i] = incl - v; }
        __syncthreads();
        if (tid == 1023) carry = incl;
        __syncthreads();
    }
}

__global__ void k_scatter_e(const int* __restrict__ src, const int* __restrict__ dst, int n) {
    int i = blockIdx.x * blockDim.x + threadIdx.x;
    if (i < n) {
        int p = atomicAdd(&g_cursor[dst[i]], 1);
        g_col[p] = src[i];
    }
}
__global__ void k_scatter_n(const int* __restrict__ batch, int n) {
    int i = blockIdx.x * blockDim.x + threadIdx.x;
    if (i < n) {
        int p = atomicAdd(&g_bcursor[batch[i]], 1);
        g_nlist[p] = i;
    }
}

// ----------------- GIN aggregation: h0 = 129*x_aff + sum_{src in adj(dst)} x_aff[src]
__global__ void k_agg(const float* __restrict__ x, const float* __restrict__ sc,
                      const float* __restrict__ sh, float* __restrict__ out, int n) {
    int w = (blockIdx.x * blockDim.x + threadIdx.x) >> 5;
    int lane = threadIdx.x & 31;
    if (w >= n) return;
    float4 s4, h4;
    if (sc) { s4 = *(const float4*)(sc + lane * 4); h4 = *(const float4*)(sh + lane * 4); }
    else { s4 = make_float4(1.f, 1.f, 1.f, 1.f); h4 = make_float4(0.f, 0.f, 0.f, 0.f); }
    const float4* xr = (const float4*)x;
    float4 self = xr[(size_t)w * 32 + lane];
    float4 acc;
    acc.x = 129.f * (self.x * s4.x + h4.x);
    acc.y = 129.f * (self.y * s4.y + h4.y);
    acc.z = 129.f * (self.z * s4.z + h4.z);
    acc.w = 129.f * (self.w * s4.w + h4.w);
    int e0 = g_rowptr[w], e1 = g_rowptr[w + 1];
    for (int base = e0; base < e1; base += 32) {
        int idx = base + lane;
        int ci = (idx < e1) ? g_col[idx] : 0;
        int m = min(32, e1 - base);
        for (int j = 0; j < m; j++) {
            int sn = __shfl_sync(0xffffffffu, ci, j);
            float4 v = xr[(size_t)sn * 32 + lane];
            acc.x += v.x * s4.x + h4.x;
            acc.y += v.y * s4.y + h4.y;
            acc.z += v.z * s4.z + h4.z;
            acc.w += v.w * s4.w + h4.w;
        }
    }
    ((float4*)out)[(size_t)w * 32 + lane] = acc;
}

// ----------------- GEMM: out = relu(affine(A) @ W + bias), accumulate col sum/sumsq
// 128-row x 128-col tile per block, 256 threads, each thread 8x8 via f32x2.
__global__ void __launch_bounds__(256, 2) k_gemm(
    const float* __restrict__ A, const float* __restrict__ sc, const float* __restrict__ sh,
    const float* __restrict__ W, const float* __restrict__ bias,
    float* __restrict__ out, float* __restrict__ csum, float* __restrict__ csq, int nrows) {
    extern __shared__ float smem[];
    float* sW = smem;            // 128*128 = 64KB
    float* sIn = smem + 16384;   // 128*64  = 32KB
    __shared__ float ssum[DD];
    __shared__ float ssq[DD];
    int tid = threadIdx.x;
    int tx = tid & 15, ty = tid >> 4;
    int row0 = blockIdx.x * 128;

    for (int i = tid; i < 4096; i += 256)
        ((float4*)sW)[i] = ((const float4*)W)[i];

    ull acc[8][4];
#pragma unroll
    for (int r = 0; r < 8; r++)
#pragma unroll
        for (int p = 0; p < 4; p++) acc[r][p] = 0ull;

    for (int kc = 0; kc < 2; kc++) {
        int k0 = kc * 64;
        if (kc) __syncthreads();
        for (int i = tid; i < 2048; i += 256) {
            int r = i >> 4, c4 = i & 15;
            int col = k0 + (c4 << 2);
            int row = row0 + r;
            float4 v;
            if (row < nrows) {
                v = *(const float4*)&A[(size_t)row * DD + col];
                if (sc) {
                    float4 s = *(const float4*)&sc[col];
                    float4 hh = *(const float4*)&sh[col];
                    v.x = v.x * s.x + hh.x; v.y = v.y * s.y + hh.y;
                    v.z = v.z * s.z + hh.z; v.w = v.w * s.w + hh.w;
                }
            } else v = make_float4(0.f, 0.f, 0.f, 0.f);
            *(float4*)&sIn[r * 64 + (c4 << 2)] = v;
        }
        __syncthreads();
#pragma unroll
        for (int kk = 0; kk < 64; kk += 4) {
            float4 av[8];
#pragma unroll
            for (int r = 0; r < 8; r++)
                av[r] = *(const float4*)&sIn[(ty * 8 + r) * 64 + kk];
#pragma unroll
            for (int j = 0; j < 4; j++) {
                const ulonglong2* wr = (const ulonglong2*)&sW[(k0 + kk + j) * DD + tx * 8];
                ulonglong2 w0 = wr[0];
                ulonglong2 w1 = wr[1];
#pragma unroll
                for (int r = 0; r < 8; r++) {
                    float a = (j == 0) ? av[r].x : (j == 1) ? av[r].y : (j == 2) ? av[r].z : av[r].w;
                    ull ap = pack2(a, a);
                    acc[r][0] = ffma2u(ap, w0.x, acc[r][0]);
                    acc[r][1] = ffma2u(ap, w0.y, acc[r][1]);
                    acc[r][2] = ffma2u(ap, w1.x, acc[r][2]);
                    acc[r][3] = ffma2u(ap, w1.y, acc[r][3]);
                }
            }
        }
    }

    float4 b0 = *(const float4*)&bias[tx * 8];
    float4 b1v = *(const float4*)&bias[tx * 8 + 4];
    float bcol[8] = {b0.x, b0.y, b0.z, b0.w, b1v.x, b1v.y, b1v.z, b1v.w};
    float psum[8], psq[8];
#pragma unroll
    for (int j = 0; j < 8; j++) { psum[j] = 0.f; psq[j] = 0.f; }

#pragma unroll
    for (int r = 0; r < 8; r++) {
        int row = row0 + ty * 8 + r;
        float o[8];
        unpack2(acc[r][0], o[0], o[1]);
        unpack2(acc[r][1], o[2], o[3]);
        unpack2(acc[r][2], o[4], o[5]);
        unpack2(acc[r][3], o[6], o[7]);
        if (row < nrows) {
#pragma unroll
            for (int j = 0; j < 8; j++) {
                float v = fmaxf(o[j] + bcol[j], 0.f);
                o[j] = v; psum[j] += v; psq[j] += v * v;
            }
            *(float4*)&out[(size_t)row * DD + tx * 8] = make_float4(o[0], o[1], o[2], o[3]);
            *(float4*)&out[(size_t)row * DD + tx * 8 + 4] = make_float4(o[4], o[5], o[6], o[7]);
        }
    }
    if (tid < DD) { ssum[tid] = 0.f; ssq[tid] = 0.f; }
    __syncthreads();
#pragma unroll
    for (int j = 0; j < 8; j++) {
        atomicAdd(&ssum[tx * 8 + j], psum[j]);
        atomicAdd(&ssq[tx * 8 + j], psq[j]);
    }
    __syncthreads();
    if (tid < DD) {
        atomicAdd(&csum[tid], ssum[tid]);
        atomicAdd(&csq[tid], ssq[tid]);
    }
}

// ----------------- BN finalize: stats -> (scale, shift); also zero the other stats pair
__global__ void k_bnfin(const float* __restrict__ cs, const float* __restrict__ cq,
                        const float* __restrict__ gam, const float* __restrict__ bet,
                        float* __restrict__ sc, float* __restrict__ sh,
                        float* __restrict__ zs, float* __restrict__ zq, float invn) {
    int t = threadIdx.x;
    float m = cs[t] * invn;
    float var = fmaxf(cq[t] * invn - m * m, 0.f);
    float s = gam[t] * rsqrtf(var + 1e-5f);
    sc[t] = s;
    sh[t] = bet[t] - m * s;
    zs[t] = 0.f; zq[t] = 0.f;
}

// ----------------- global_add_pool via node-CSR gather (affine sc2/sh2 on load)
__global__ void k_pool(const float* __restrict__ y, int slice) {
    int w = (blockIdx.x * blockDim.x + threadIdx.x) >> 5;
    int lane = threadIdx.x & 31;
    if (w >= GG) return;
    float4 s4 = *(const float4*)(g_sc2 + lane * 4);
    float4 h4 = *(const float4*)(g_sh2 + lane * 4);
    const float4* yr = (const float4*)y;
    float4 acc = make_float4(0.f, 0.f, 0.f, 0.f);
    int e0 = g_browptr[w], e1 = g_browptr[w + 1];
    for (int base = e0; base < e1; base += 32) {
        int idx = base + lane;
        int ni = (idx < e1) ? g_nlist[idx] : 0;
        int m = min(32, e1 - base);
        for (int j = 0; j < m; j++) {
            int nn = __shfl_sync(0xffffffffu, ni, j);
            float4 v = yr[(size_t)nn * 32 + lane];
            acc.x += v.x * s4.x + h4.x;
            acc.y += v.y * s4.y + h4.y;
            acc.z += v.z * s4.z + h4.z;
            acc.w += v.w * s4.w + h4.w;
        }
    }
    *(float4*)&g_feats[w * (BB * DD) + slice * DD + lane * 4] = acc;
}

// ----------------- classifier BN stats over graphs
__global__ void k_fstats(const float* __restrict__ bng, const float* __restrict__ bnb) {
    int c = blockIdx.x * blockDim.x + threadIdx.x;   // 0..639
    float s = 0.f, q = 0.f;
    for (int r = 0; r < GG; r++) {
        float v = g_feats[r * (BB * DD) + c];
        s += v; q += v * v;
    }
    float m = s * (1.f / GG);
    float var = fmaxf(q * (1.f / GG) - m * m, 0.f);
    float scv = bng[c] * rsqrtf(var + 1e-5f);
    g_fs[c] = scv;
    g_fh[c] = bnb[c] - m * scv;
}

// ----------------- classifier: BN -> relu(f@Wc1+bc1) -> @Wc2+bc2 -> log_softmax
__global__ void k_cls(const float* __restrict__ Wc1, const float* __restrict__ bc1,
                      const float* __restrict__ Wc2, const float* __restrict__ bc2,
                      float* __restrict__ out) {
    __shared__ float f[BB * DD];
    __shared__ float h[DD];
    __shared__ float lg[CC];
    __shared__ float lse;
    int g = blockIdx.x, t = threadIdx.x;
    for (int j = t; j < BB * DD; j += DD)
        f[j] = g_feats[g * (BB * DD) + j] * g_fs[j] + g_fh[j];
    __syncthreads();
    float a = bc1[t];
#pragma unroll 8
    for (int k = 0; k < BB * DD; k++) a += f[k] * Wc1[k * DD + t];
    h[t] = fmaxf(a, 0.f);
    __syncthreads();
    if (t < CC) {
        float l = bc2[t];
#pragma unroll 8
        for (int k = 0; k < DD; k++) l += h[k] * Wc2[k * CC + t];
        lg[t] = l;
    }
    __syncthreads();
    if (t == 0) {
        float m = -1e30f;
        for (int c = 0; c < CC; c++) m = fmaxf(m, lg[c]);
        float se = 0.f;
        for (int c = 0; c < CC; c++) se += expf(lg[c] - m);
        lse = m + logf(se);
    }
    __syncthreads();
    if (t < CC) out[g * CC + t] = lg[t] - lse;
}

// ----------------- host launch -----------------
extern "C" void kernel_launch(void* const* d_in, const int* in_sizes, int n_in,
                              void* d_out, int out_size) {
    const float* x   = (const float*)d_in[0];
    const int*   ei  = (const int*)d_in[1];
    const int*   bat = (const int*)d_in[2];
    const float* W1  = (const float*)d_in[3];
    const float* b1  = (const float*)d_in[4];
    const float* g1  = (const float*)d_in[5];
    const float* be1 = (const float*)d_in[6];
    const float* W2  = (const float*)d_in[7];
    const float* b2  = (const float*)d_in[8];
    const float* g2  = (const float*)d_in[9];
    const float* be2 = (const float*)d_in[10];
    const float* bng = (const float*)d_in[11];
    const float* bnb = (const float*)d_in[12];
    const float* Wc1 = (const float*)d_in[13];
    const float* bc1 = (const float*)d_in[14];
    const float* Wc2 = (const float*)d_in[15];
    const float* bc2 = (const float*)d_in[16];
    float* out = (float*)d_out;

    int n = in_sizes[0] / DD;
    int e = in_sizes[1] / 2;

    float *bufA, *bufB, *bufC, *cs1, *cq1, *cs2, *cq2, *sc1, *sh1, *sc2, *sh2;
    int *cnt, *rowptr, *cursor, *bcnt, *browptr, *bcursor;
    cudaGetSymbolAddress((void**)&bufA, g_bufA);
    cudaGetSymbolAddress((void**)&bufB, g_bufB);
    cudaGetSymbolAddress((void**)&bufC, g_bufC);
    cudaGetSymbolAddress((void**)&cs1, g_cs1);
    cudaGetSymbolAddress((void**)&cq1, g_cq1);
    cudaGetSymbolAddress((void**)&cs2, g_cs2);
    cudaGetSymbolAddress((void**)&cq2, g_cq2);
    cudaGetSymbolAddress((void**)&sc1, g_sc1);
    cudaGetSymbolAddress((void**)&sh1, g_sh1);
    cudaGetSymbolAddress((void**)&sc2, g_sc2);
    cudaGetSymbolAddress((void**)&sh2, g_sh2);
    cudaGetSymbolAddress((void**)&cnt, g_cnt);
    cudaGetSymbolAddress((void**)&rowptr, g_rowptr);
    cudaGetSymbolAddress((void**)&cursor, g_cursor);
    cudaGetSymbolAddress((void**)&bcnt, g_bcnt);
    cudaGetSymbolAddress((void**)&browptr, g_browptr);
    cudaGetSymbolAddress((void**)&bcursor, g_bcursor);

    cudaFuncSetAttribute(k_gemm, cudaFuncAttributeMaxDynamicSharedMemorySize, 98304);

    const int TB = 256;
    // CSR build (by dst for aggregation, by batch for pooling) + zero stats
    k_init<<<(n + TB - 1) / TB, TB>>>(n);
    k_hist<<<(e + TB - 1) / TB, TB>>>(ei + e, cnt, e);   // dst row of edge_index
    k_hist<<<(n + TB - 1) / TB, TB>>>(bat, bcnt, n);
    k_scan<<<1, 1024>>>(cnt, rowptr, cursor, n);
    k_scan<<<1, 1024>>>(bcnt, browptr, bcursor, GG);
    k_scatter_e<<<(e + TB - 1) / TB, TB>>>(ei, ei + e, e);
    k_scatter_n<<<(n + TB - 1) / TB, TB>>>(bat, n);

    int agg_blocks = (n + 7) / 8;
    int gemm_blocks = (n + 127) / 128;
    float invn = 1.f / (float)n;

    for (int i = 0; i < BB; i++) {
        const float* xin = (i == 0) ? x : bufC;
        const float* asc = (i == 0) ? (const float*)0 : sc2;
        const float* ash = (i == 0) ? (const float*)0 : sh2;
        k_agg<<<agg_blocks, TB>>>(xin, asc, ash, bufA, n);
        k_gemm<<<gemm_blocks, TB, 98304>>>(bufA, (const float*)0, (const float*)0,
                                           W1 + (size_t)i * DD * DD, b1 + i * DD,
                                           bufB, cs1, cq1, n);
        k_bnfin<<<1, DD>>>(cs1, cq1, g1 + i * DD, be1 + i * DD, sc1, sh1, cs2, cq2, invn);
        k_gemm<<<gemm_blocks, TB, 98304>>>(bufB, sc1, sh1,
                                           W2 + (size_t)i * DD * DD, b2 + i * DD,
                                           bufC, cs2, cq2, n);
        k_bnfin<<<1, DD>>>(cs2, cq2, g2 + i * DD, be2 + i * DD, sc2, sh2, cs1, cq1, invn);
        k_pool<<<(GG + 7) / 8, TB>>>(bufC, i);
    }

    k_fstats<<<BB, DD>>>(bng, bnb);
    k_cls<<<GG, DD>>>(Wc1, bc1, Wc2, bc2, out);
    (void)out_size; (void)n_in;
}